// round 5
// baseline (speedup 1.0000x reference)
#include <cuda_runtime.h>
#include <cuda_bf16.h>
#include <math.h>
#include <stdint.h>

// ---------------- problem constants ----------------
#define BSZ 32
#define TT 197           // tokens
#define TD 768           // token dim
#define NH 12            // heads
#define HD 64            // head dim
#define NB 12            // blocks
#define MD 3072          // mlp dim
#define OD 1000          // out dim
#define NPATCH 196
#define M_TOK (BSZ*TT)   // 6304
#define M_PATCH (BSZ*NPATCH) // 6272
#define ATT_SCALE 0.125f
#define LN_EPS 1e-5f

// ---------------- scratch (device globals, no allocation) ----------------
__device__ float g_x[M_TOK*TD];
__device__ float g_h[M_TOK*TD];
__device__ float g_q[M_TOK*TD];
__device__ float g_k[M_TOK*TD];
__device__ float g_v[M_TOK*TD];
__device__ float g_mlp[(size_t)M_TOK*MD];
__device__ float g_patches[(size_t)M_PATCH*TD];
// transposed weights: [embedT 768x768][12 x m1T 3072x768][12 x m2T 768x3072]
#define WT_EMBED_OFF 0
#define WT_M1_OFF    (768*768)
#define WT_M2_OFF    (768*768 + 12*768*3072)
__device__ float g_wT[768*768 + 24*768*3072];

// ---------------- small reductions ----------------
__device__ __forceinline__ float warpSum(float v){
    #pragma unroll
    for (int o=16;o;o>>=1) v += __shfl_xor_sync(0xffffffffu, v, o);
    return v;
}
__device__ __forceinline__ float warpMax(float v){
    #pragma unroll
    for (int o=16;o;o>>=1) v = fmaxf(v, __shfl_xor_sync(0xffffffffu, v, o));
    return v;
}
__device__ __forceinline__ float blockSum256(float v){
    __shared__ float red[8];
    __shared__ float total;
    int lane = threadIdx.x & 31, w = threadIdx.x >> 5;
    v = warpSum(v);
    if (lane == 0) red[w] = v;
    __syncthreads();
    if (threadIdx.x == 0){ float s=0.f; for(int i=0;i<8;i++) s += red[i]; total = s; }
    __syncthreads();
    float r = total;
    __syncthreads();
    return r;
}
__device__ __forceinline__ float blockMax256(float v){
    __shared__ float red[8];
    __shared__ float total;
    int lane = threadIdx.x & 31, w = threadIdx.x >> 5;
    v = warpMax(v);
    if (lane == 0) red[w] = v;
    __syncthreads();
    if (threadIdx.x == 0){ float s=-1e30f; for(int i=0;i<8;i++) s = fmaxf(s, red[i]); total = s; }
    __syncthreads();
    float r = total;
    __syncthreads();
    return r;
}

// ---------------- tf32 / async helpers ----------------
__device__ __forceinline__ unsigned f2tf(float x){
    unsigned u; asm("cvt.rna.tf32.f32 %0, %1;" : "=r"(u) : "f"(x)); return u;
}
__device__ __forceinline__ float rnd_tf32(float x){ return __uint_as_float(f2tf(x)); }

__device__ __forceinline__ unsigned smem_u32(const void* p){
    return (unsigned)__cvta_generic_to_shared(p);
}
__device__ __forceinline__ void cp_async16(unsigned dst, const void* src, int src_bytes){
    asm volatile("cp.async.cg.shared.global [%0], [%1], 16, %2;\n"
                 :: "r"(dst), "l"(src), "r"(src_bytes));
}
__device__ __forceinline__ void cp_commit(){ asm volatile("cp.async.commit_group;\n"); }
template<int N>
__device__ __forceinline__ void cp_wait(){ asm volatile("cp.async.wait_group %0;\n" :: "n"(N)); }

__device__ __forceinline__ void ldmx4(uint32_t& r0, uint32_t& r1, uint32_t& r2, uint32_t& r3,
                                      uint32_t addr){
    asm volatile("ldmatrix.sync.aligned.m8n8.x4.shared.b16 {%0,%1,%2,%3}, [%4];"
                 : "=r"(r0), "=r"(r1), "=r"(r2), "=r"(r3) : "r"(addr));
}

// ---------------- patchify (tf32-rounded: feeds embed GEMM) ----------------
__global__ void patchify_kernel(const float* __restrict__ img){
    int idx = blockIdx.x*blockDim.x + threadIdx.x;
    if (idx >= M_PATCH*TD) return;
    int d = idx % TD;
    int mp = idx / TD;
    int b = mp / NPATCH;
    int p = mp % NPATCH;
    int py = p / 14, px = p % 14;
    int c = d >> 8;
    int r = d & 255;
    int iy = r >> 4, ix = r & 15;
    g_patches[idx] = rnd_tf32(img[ (((size_t)(b*3 + c)*224) + py*16 + iy)*224 + px*16 + ix ]);
}

// ---------------- weight transpose (+ tf32 rounding) ----------------
// src [R][C] row-major -> dst [C][R] row-major
__global__ void transpose_kernel(const float* __restrict__ src, float* __restrict__ dst,
                                 int R, int C){
    __shared__ float t[32][33];
    int bx = blockIdx.x*32, by = blockIdx.y*32;
    int x = bx + threadIdx.x;
    #pragma unroll
    for (int j = 0; j < 32; j += 8){
        int y = by + threadIdx.y + j;
        if (x < C && y < R) t[threadIdx.y+j][threadIdx.x] = src[(size_t)y*C + x];
    }
    __syncthreads();
    int x2 = by + threadIdx.x;
    #pragma unroll
    for (int j = 0; j < 32; j += 8){
        int y2 = bx + threadIdx.y + j;
        if (x2 < R && y2 < C) dst[(size_t)y2*R + x2] = rnd_tf32(t[threadIdx.x][threadIdx.y+j]);
    }
}

// ---------------- cls + pos-emb assembly ----------------
__global__ void assemble_kernel(const float* __restrict__ vcls, const float* __restrict__ tokens){
    int idx = blockIdx.x*blockDim.x + threadIdx.x;
    if (idx >= M_TOK*TD) return;
    int d = idx % TD;
    int m = idx / TD;
    int b = m / TT;
    int s = m % TT;
    float val = (s == 0) ? vcls[d] : tokens[(size_t)(b*NPATCH + s - 1)*TD + d];
    float je = (float)(d & ~1);
    float ang = (float)s * exp2f(-je * (13.287712379549449f / 197.0f));
    val += (d & 1) ? cosf(ang) : sinf(ang);
    g_x[idx] = val;
}

// ---------------- layernorm (tf32-rounded out: feeds GEMMs/QKV) ----------------
__global__ void layernorm_kernel(const float* __restrict__ x, float* __restrict__ out,
                                 const float* __restrict__ g, const float* __restrict__ b){
    __shared__ float sdata[TD];
    int row = blockIdx.x;
    const float* xr = x + (size_t)row*TD;
    float local = 0.f;
    for (int i = threadIdx.x; i < TD; i += 256){ float v = xr[i]; sdata[i] = v; local += v; }
    float mean = blockSum256(local) * (1.0f/TD);
    float lv = 0.f;
    for (int i = threadIdx.x; i < TD; i += 256){ float t = sdata[i]-mean; lv += t*t; }
    float var = blockSum256(lv) * (1.0f/TD);
    float rstd = rsqrtf(var + LN_EPS);
    float* orow = out + (size_t)row*TD;
    for (int i = threadIdx.x; i < TD; i += 256)
        orow[i] = rnd_tf32((sdata[i]-mean)*rstd*g[i] + b[i]);
}

// ---------------- per-head QKV projection ----------------
__global__ void qkv_kernel(const float* __restrict__ Wq, const float* __restrict__ bq,
                           const float* __restrict__ Wk, const float* __restrict__ bk,
                           const float* __restrict__ Wv, const float* __restrict__ bv){
    __shared__ float Hs[64][65];
    __shared__ float Ws[64][64];
    int h = blockIdx.y;
    int m0 = blockIdx.x * 64;
    int tid = threadIdx.x;

    for (int i = tid; i < 64*64; i += 256){
        int r = i >> 6, cc = i & 63;
        int row = m0 + r;
        Hs[r][cc] = (row < M_TOK) ? g_h[(size_t)row*TD + h*64 + cc] : 0.f;
    }
    const float* Wp[3] = {Wq, Wk, Wv};
    const float* bp[3] = {bq, bk, bv};
    float* op[3] = {g_q, g_k, g_v};
    int ty = tid >> 4, tx = tid & 15;

    for (int m = 0; m < 3; m++){
        __syncthreads();
        const float* W = Wp[m] + (size_t)h*64*64;
        for (int i = tid; i < 64*64; i += 256) Ws[i>>6][i&63] = W[i];
        __syncthreads();
        float acc[4][4];
        #pragma unroll
        for (int i=0;i<4;i++)
            #pragma unroll
            for (int j=0;j<4;j++) acc[i][j]=0.f;
        #pragma unroll 8
        for (int kd = 0; kd < 64; kd++){
            float a[4], bb[4];
            #pragma unroll
            for (int i=0;i<4;i++) a[i] = Hs[ty*4+i][kd];
            #pragma unroll
            for (int j=0;j<4;j++) bb[j] = Ws[kd][tx*4+j];
            #pragma unroll
            for (int i=0;i<4;i++)
                #pragma unroll
                for (int j=0;j<4;j++) acc[i][j] = fmaf(a[i], bb[j], acc[i][j]);
        }
        #pragma unroll
        for (int i=0;i<4;i++){
            int row = m0 + ty*4 + i;
            if (row >= M_TOK) continue;
            #pragma unroll
            for (int j=0;j<4;j++){
                int e = tx*4 + j;
                op[m][(size_t)row*TD + h*64 + e] = acc[i][j] + bp[m][h*64 + e];
            }
        }
    }
}

// ---------------- fused attention (per (b,h)), residual add into x ----------------
__global__ void attn_kernel(){
    extern __shared__ float sm[];
    float* Kt = sm;                 // [64][200]
    float* Vs = Kt + 64*200;        // [197][64]
    float* q8 = Vs + TT*64;         // [8][64]
    float* p8 = q8 + 8*64;          // [8][224]

    int h = blockIdx.x, b = blockIdx.y;
    int tid = threadIdx.x;
    size_t base = ((size_t)b*TT)*TD + h*64;

    for (int i = tid; i < TT*64; i += 256){
        int k = i >> 6, d = i & 63;
        float kv = g_k[base + (size_t)k*TD + d];
        Kt[d*200 + k] = kv;
        Vs[i] = g_v[base + (size_t)k*TD + d];
    }
    __syncthreads();

    int w = tid >> 5, lane = tid & 31;
    float* qr = q8 + w*64;
    float* pr = p8 + w*224;

    for (int s = w; s < TT; s += 8){
        qr[lane]      = g_q[base + (size_t)s*TD + lane];
        qr[lane + 32] = g_q[base + (size_t)s*TD + lane + 32];
        __syncwarp();
        float lmax = -1e30f;
        for (int k = lane; k < TT; k += 32){
            float dot = 0.f;
            #pragma unroll
            for (int d = 0; d < 64; d++) dot = fmaf(qr[d], Kt[d*200 + k], dot);
            dot *= ATT_SCALE;
            pr[k] = dot;
            lmax = fmaxf(lmax, dot);
        }
        lmax = warpMax(lmax);
        float lsum = 0.f;
        for (int k = lane; k < TT; k += 32){
            float e = expf(pr[k] - lmax);
            pr[k] = e;
            lsum += e;
        }
        lsum = warpSum(lsum);
        float inv = 1.0f / lsum;
        __syncwarp();
        float acc0 = 0.f, acc1 = 0.f;
        for (int k = 0; k < TT; k++){
            float p = pr[k];
            acc0 = fmaf(p, Vs[k*64 + lane],      acc0);
            acc1 = fmaf(p, Vs[k*64 + lane + 32], acc1);
        }
        size_t xi = base + (size_t)s*TD;
        g_x[xi + lane]      += acc0 * inv;
        g_x[xi + lane + 32] += acc1 * inv;
        __syncwarp();
    }
}

// ---------------- tf32 MMA GEMM, ldmatrix operand staging ----------------
// C (epi) A[M,K] @ BT[N,K]^T + bias ; epi: 0 store, 1 gelu(+tf32 round), 2 residual +=
// CTA tile 128x128, k-tile 32; 256 threads = 8 warps (4x2), warp tile 32x64.
// A and BT tiles both stored [dim128][32k] with 36-float (144B) row stride:
// rows 0..7 hit 8 distinct 16B segments -> conflict-free ldmatrix.
// Inputs MUST be pre-rounded to tf32 (RNA) by their producers.
#define GSTRIDE 36
#define GTILE_BYTES (128*GSTRIDE*4)      // 18432
#define GEMM_SMEM (4*GTILE_BYTES)        // A0 A1 B0 B1 = 73728

__global__ void __launch_bounds__(256)
tf32gemm_kernel(const float* __restrict__ A, const float* __restrict__ BT,
                const float* __restrict__ bias, float* __restrict__ C,
                int M, int N, int K, int epi){
    extern __shared__ float smg[];
    uint32_t sb = smem_u32(smg);
    const uint32_t AOFF[2] = {0u, (uint32_t)GTILE_BYTES};
    const uint32_t BOFF[2] = {2u*GTILE_BYTES, 3u*GTILE_BYTES};

    int tid  = threadIdx.x;
    int lane = tid & 31;
    int warp = tid >> 5;
    int warpM = warp >> 1;          // 0..3
    int warpN = warp & 1;           // 0..1
    int row0 = blockIdx.y * 128;
    int col0 = blockIdx.x * 128;

    float cf[2][8][4];
    #pragma unroll
    for (int mi=0;mi<2;mi++)
        #pragma unroll
        for (int ni=0;ni<8;ni++)
            #pragma unroll
            for (int j=0;j<4;j++) cf[mi][ni][j] = 0.f;

    // load mapping: thread handles row tid>>1, 4 chunks of 16B in half (tid&1)
    int ldrow = tid >> 1;
    int ldc0  = (tid & 1) * 16;     // float offset within 32-float row
    const float* aSrc = A + (size_t)(row0 + ldrow)*K + ldc0;
    int aSz = (row0 + ldrow < M) ? 16 : 0;
    const float* bSrc = BT + (size_t)(col0 + ldrow)*K + ldc0;
    uint32_t stDst = (uint32_t)(ldrow*GSTRIDE + ldc0)*4u;

    int KT = K >> 5;

    // prologue: tile 0 -> buf 0
    #pragma unroll
    for (int c = 0; c < 4; c++){
        cp_async16(sb + AOFF[0] + stDst + c*16u, aSrc + c*4, aSz);
        cp_async16(sb + BOFF[0] + stDst + c*16u, bSrc + c*4, 16);
    }
    cp_commit();

    // ldmatrix base addresses (per-lane)
    // A call (mi, step): lanes 0-15 rows m0+ (lane&15), kw +(lane>>4)*16B ; +step*32B
    uint32_t aLM = (uint32_t)((warpM*32 + (lane & 15))*GSTRIDE)*4u + ((lane >> 4) ? 16u : 0u);
    // B call (ni, h16): lanes rows n0+(lane&7), +(lane>>3)*16B ; +h16*64B
    uint32_t bLM = (uint32_t)((warpN*64 + (lane & 7))*GSTRIDE)*4u + (uint32_t)(lane >> 3)*16u;

    for (int kt = 0; kt < KT; kt++){
        int buf = kt & 1;
        if (kt + 1 < KT){
            int nb = buf ^ 1;
            int kk = (kt + 1) << 5;
            #pragma unroll
            for (int c = 0; c < 4; c++){
                cp_async16(sb + AOFF[nb] + stDst + c*16u, aSrc + kk + c*4, aSz);
                cp_async16(sb + BOFF[nb] + stDst + c*16u, bSrc + kk + c*4, 16);
            }
            cp_commit();
            cp_wait<1>();
        } else {
            cp_wait<0>();
        }
        __syncthreads();

        uint32_t ab = sb + AOFF[buf] + aLM;
        uint32_t bb = sb + BOFF[buf] + bLM;

        #pragma unroll
        for (int h16 = 0; h16 < 2; h16++){
            uint32_t af[2][2][4];   // [mi][step][frag]
            #pragma unroll
            for (int mi = 0; mi < 2; mi++){
                uint32_t base = ab + (uint32_t)(mi*16*GSTRIDE)*4u + (uint32_t)h16*64u;
                ldmx4(af[mi][0][0], af[mi][0][1], af[mi][0][2], af[mi][0][3], base);
                ldmx4(af[mi][1][0], af[mi][1][1], af[mi][1][2], af[mi][1][3], base + 32u);
            }
            uint32_t bf[8][4];      // {b0s0,b1s0,b0s8,b1s8}
            #pragma unroll
            for (int ni = 0; ni < 8; ni++){
                uint32_t base = bb + (uint32_t)(ni*8*GSTRIDE)*4u + (uint32_t)h16*64u;
                ldmx4(bf[ni][0], bf[ni][1], bf[ni][2], bf[ni][3], base);
            }
            #pragma unroll
            for (int st = 0; st < 2; st++)
                #pragma unroll
                for (int mi = 0; mi < 2; mi++)
                    #pragma unroll
                    for (int ni = 0; ni < 8; ni++){
                        asm volatile(
                            "mma.sync.aligned.m16n8k8.row.col.f32.tf32.tf32.f32 "
                            "{%0,%1,%2,%3}, {%4,%5,%6,%7}, {%8,%9}, {%0,%1,%2,%3};"
                            : "+f"(cf[mi][ni][0]), "+f"(cf[mi][ni][1]),
                              "+f"(cf[mi][ni][2]), "+f"(cf[mi][ni][3])
                            : "r"(af[mi][st][0]), "r"(af[mi][st][1]),
                              "r"(af[mi][st][2]), "r"(af[mi][st][3]),
                              "r"(bf[ni][st*2]), "r"(bf[ni][st*2+1]));
                    }
        }
        __syncthreads();
    }

    // epilogue
    #pragma unroll
    for (int mi = 0; mi < 2; mi++){
        int rbase = row0 + warpM*32 + mi*16 + (lane >> 2);
        #pragma unroll
        for (int ni = 0; ni < 8; ni++){
            int cbase = col0 + warpN*64 + ni*8 + (lane & 3)*2;
            #pragma unroll
            for (int hh = 0; hh < 2; hh++){
                int r = rbase + hh*8;
                if (r >= M) continue;
                #pragma unroll
                for (int jj = 0; jj < 2; jj++){
                    int c = cbase + jj;
                    float v = cf[mi][ni][hh*2+jj] + bias[c];
                    size_t idx = (size_t)r*N + c;
                    if (epi == 1){
                        C[idx] = rnd_tf32(0.5f*v*(1.0f + erff(v*0.70710678118654752f)));
                    } else if (epi == 2){
                        C[idx] += v;
                    } else {
                        C[idx] = v;
                    }
                }
            }
        }
    }
}

// ---------------- classifier head + softmax ----------------
__global__ void classifier_kernel(const float* __restrict__ Wout, const float* __restrict__ bout,
                                  float* __restrict__ out){
    __shared__ float xs[TD];
    __shared__ float lg[OD];
    int b = blockIdx.x;
    int tid = threadIdx.x;
    for (int i = tid; i < TD; i += 256) xs[i] = g_x[((size_t)b*TT)*TD + i];
    __syncthreads();
    for (int n = tid; n < OD; n += 256){
        float s = bout[n];
        for (int d = 0; d < TD; d++) s = fmaf(xs[d], Wout[(size_t)d*OD + n], s);
        lg[n] = s;
    }
    __syncthreads();
    float lm = -1e30f;
    for (int n = tid; n < OD; n += 256) lm = fmaxf(lm, lg[n]);
    lm = blockMax256(lm);
    float ls = 0.f;
    for (int n = tid; n < OD; n += 256){
        float e = expf(lg[n] - lm);
        lg[n] = e;
        ls += e;
    }
    ls = blockSum256(ls);
    float inv = 1.0f / ls;
    for (int n = tid; n < OD; n += 256) out[(size_t)b*OD + n] = lg[n] * inv;
}

// ---------------- host orchestration ----------------
extern "C" void kernel_launch(void* const* d_in, const int* in_sizes, int n_in,
                              void* d_out, int out_size){
    const float* images  = (const float*)d_in[0];
    const float* W_embed = (const float*)d_in[1];
    const float* b_embed = (const float*)d_in[2];
    const float* v_class = (const float*)d_in[3];
    const float* ln1_g   = (const float*)d_in[4];
    const float* ln1_b   = (const float*)d_in[5];
    const float* ln2_g   = (const float*)d_in[6];
    const float* ln2_b   = (const float*)d_in[7];
    const float* Wq      = (const float*)d_in[8];
    const float* bq      = (const float*)d_in[9];
    const float* Wk      = (const float*)d_in[10];
    const float* bk      = (const float*)d_in[11];
    const float* Wv      = (const float*)d_in[12];
    const float* bv      = (const float*)d_in[13];
    const float* Wm1     = (const float*)d_in[14];
    const float* bm1     = (const float*)d_in[15];
    const float* Wm2     = (const float*)d_in[16];
    const float* bm2     = (const float*)d_in[17];
    const float* Wout    = (const float*)d_in[18];
    const float* bout    = (const float*)d_in[19];
    float* out = (float*)d_out;

    float *px, *ph, *pmlp, *ppatch, *pwT;
    cudaGetSymbolAddress((void**)&px, g_x);
    cudaGetSymbolAddress((void**)&ph, g_h);
    cudaGetSymbolAddress((void**)&pmlp, g_mlp);
    cudaGetSymbolAddress((void**)&ppatch, g_patches);
    cudaGetSymbolAddress((void**)&pwT, g_wT);

    const int ATT_SMEM = (64*200 + TT*64 + 8*64 + 8*224) * 4; // 110848 bytes
    cudaFuncSetAttribute(attn_kernel, cudaFuncAttributeMaxDynamicSharedMemorySize, ATT_SMEM);
    cudaFuncSetAttribute(tf32gemm_kernel, cudaFuncAttributeMaxDynamicSharedMemorySize, GEMM_SMEM);

    // weight transposes (tf32-rounded), once per launch
    {
        dim3 blk(32, 8);
        transpose_kernel<<<dim3(TD/32, TD/32), blk>>>(W_embed, pwT + WT_EMBED_OFF, TD, TD);
        for (int l = 0; l < NB; l++){
            transpose_kernel<<<dim3(MD/32, TD/32), blk>>>(Wm1 + (size_t)l*TD*MD,
                pwT + WT_M1_OFF + (size_t)l*TD*MD, TD, MD);
            transpose_kernel<<<dim3(TD/32, MD/32), blk>>>(Wm2 + (size_t)l*MD*TD,
                pwT + WT_M2_OFF + (size_t)l*MD*TD, MD, TD);
        }
    }

    // patchify + embed
    patchify_kernel<<<(M_PATCH*TD + 255)/256, 256>>>(images);
    {
        dim3 g(TD/128, (M_PATCH + 127)/128);
        tf32gemm_kernel<<<g, 256, GEMM_SMEM>>>(ppatch, pwT + WT_EMBED_OFF, b_embed, pmlp,
                                               M_PATCH, TD, TD, 0);
    }
    assemble_kernel<<<(M_TOK*TD + 255)/256, 256>>>(v_class, pmlp);

    for (int l = 0; l < NB; l++){
        layernorm_kernel<<<M_TOK, 256>>>(px, ph, ln1_g + l*TD, ln1_b + l*TD);
        {
            dim3 g((M_TOK + 63)/64, NH);
            qkv_kernel<<<g, 256>>>(Wq + (size_t)l*NH*64*64, bq + (size_t)l*NH*64,
                                   Wk + (size_t)l*NH*64*64, bk + (size_t)l*NH*64,
                                   Wv + (size_t)l*NH*64*64, bv + (size_t)l*NH*64);
        }
        attn_kernel<<<dim3(NH, BSZ), 256, ATT_SMEM>>>();
        layernorm_kernel<<<M_TOK, 256>>>(px, ph, ln2_g + l*TD, ln2_b + l*TD);
        {
            dim3 g(MD/128, (M_TOK + 127)/128);
            tf32gemm_kernel<<<g, 256, GEMM_SMEM>>>(ph, pwT + WT_M1_OFF + (size_t)l*TD*MD,
                                                   bm1 + (size_t)l*MD, pmlp,
                                                   M_TOK, MD, TD, 1);
        }
        {
            dim3 g(TD/128, (M_TOK + 127)/128);
            tf32gemm_kernel<<<g, 256, GEMM_SMEM>>>(pmlp, pwT + WT_M2_OFF + (size_t)l*MD*TD,
                                                   bm2 + (size_t)l*TD, px,
                                                   M_TOK, TD, MD, 2);
        }
    }

    classifier_kernel<<<BSZ, 256>>>(Wout, bout, out);
}

// round 6
// speedup vs baseline: 1.1655x; 1.1655x over previous
#include <cuda_runtime.h>
#include <cuda_bf16.h>
#include <math.h>
#include <stdint.h>

// ---------------- problem constants ----------------
#define BSZ 32
#define TT 197           // tokens
#define TD 768           // token dim
#define NH 12            // heads
#define HD 64            // head dim
#define NB 12            // blocks
#define MD 3072          // mlp dim
#define OD 1000          // out dim
#define NPATCH 196
#define M_TOK (BSZ*TT)   // 6304
#define M_PATCH (BSZ*NPATCH) // 6272
#define ATT_SCALE 0.125f
#define LN_EPS 1e-5f

// ---------------- scratch (device globals, no allocation) ----------------
__device__ float g_x[M_TOK*TD];
__device__ float g_h[M_TOK*TD];
__device__ float g_q[M_TOK*TD];
__device__ float g_k[M_TOK*TD];
__device__ float g_v[M_TOK*TD];
__device__ float g_mlp[(size_t)M_TOK*MD];
__device__ float g_patches[(size_t)M_PATCH*TD];
// tf32-rounded weights (same orientation as inputs):
// [embed 768x768][m1 12x768x3072][m2 12x3072x768]
#define WR_EMBED_OFF 0
#define WR_M1_OFF    (768*768)
#define WR_M2_OFF    (768*768 + 12*768*3072)
__device__ float g_wR[768*768 + 24*768*3072];

// ---------------- small reductions ----------------
__device__ __forceinline__ float warpSum(float v){
    #pragma unroll
    for (int o=16;o;o>>=1) v += __shfl_xor_sync(0xffffffffu, v, o);
    return v;
}
__device__ __forceinline__ float warpMax(float v){
    #pragma unroll
    for (int o=16;o;o>>=1) v = fmaxf(v, __shfl_xor_sync(0xffffffffu, v, o));
    return v;
}
__device__ __forceinline__ float blockSum256(float v){
    __shared__ float red[8];
    __shared__ float total;
    int lane = threadIdx.x & 31, w = threadIdx.x >> 5;
    v = warpSum(v);
    if (lane == 0) red[w] = v;
    __syncthreads();
    if (threadIdx.x == 0){ float s=0.f; for(int i=0;i<8;i++) s += red[i]; total = s; }
    __syncthreads();
    float r = total;
    __syncthreads();
    return r;
}
__device__ __forceinline__ float blockMax256(float v){
    __shared__ float red[8];
    __shared__ float total;
    int lane = threadIdx.x & 31, w = threadIdx.x >> 5;
    v = warpMax(v);
    if (lane == 0) red[w] = v;
    __syncthreads();
    if (threadIdx.x == 0){ float s=-1e30f; for(int i=0;i<8;i++) s = fmaxf(s, red[i]); total = s; }
    __syncthreads();
    float r = total;
    __syncthreads();
    return r;
}

// ---------------- tf32 / async helpers ----------------
__device__ __forceinline__ unsigned f2tf(float x){
    unsigned u; asm("cvt.rna.tf32.f32 %0, %1;" : "=r"(u) : "f"(x)); return u;
}
__device__ __forceinline__ float rnd_tf32(float x){ return __uint_as_float(f2tf(x)); }

__device__ __forceinline__ unsigned smem_u32(const void* p){
    return (unsigned)__cvta_generic_to_shared(p);
}
__device__ __forceinline__ void cp_async16(unsigned dst, const void* src, int src_bytes){
    asm volatile("cp.async.cg.shared.global [%0], [%1], 16, %2;\n"
                 :: "r"(dst), "l"(src), "r"(src_bytes));
}
__device__ __forceinline__ void cp_commit(){ asm volatile("cp.async.commit_group;\n"); }
template<int N>
__device__ __forceinline__ void cp_wait(){ asm volatile("cp.async.wait_group %0;\n" :: "n"(N)); }

// ---------------- weight round-copy (fp32 -> tf32-rounded fp32) ----------------
__global__ void roundcopy_kernel(const float* __restrict__ src, float* __restrict__ dst,
                                 size_t n){
    size_t i = (size_t)blockIdx.x*blockDim.x + threadIdx.x;
    size_t stride = (size_t)gridDim.x*blockDim.x;
    for (; i < n; i += stride) dst[i] = rnd_tf32(src[i]);
}

// ---------------- patchify (tf32-rounded: feeds embed GEMM) ----------------
__global__ void patchify_kernel(const float* __restrict__ img){
    int idx = blockIdx.x*blockDim.x + threadIdx.x;
    if (idx >= M_PATCH*TD) return;
    int d = idx % TD;
    int mp = idx / TD;
    int b = mp / NPATCH;
    int p = mp % NPATCH;
    int py = p / 14, px = p % 14;
    int c = d >> 8;
    int r = d & 255;
    int iy = r >> 4, ix = r & 15;
    g_patches[idx] = rnd_tf32(img[ (((size_t)(b*3 + c)*224) + py*16 + iy)*224 + px*16 + ix ]);
}

// ---------------- cls + pos-emb assembly ----------------
__global__ void assemble_kernel(const float* __restrict__ vcls, const float* __restrict__ tokens){
    int idx = blockIdx.x*blockDim.x + threadIdx.x;
    if (idx >= M_TOK*TD) return;
    int d = idx % TD;
    int m = idx / TD;
    int b = m / TT;
    int s = m % TT;
    float val = (s == 0) ? vcls[d] : tokens[(size_t)(b*NPATCH + s - 1)*TD + d];
    float je = (float)(d & ~1);
    float ang = (float)s * exp2f(-je * (13.287712379549449f / 197.0f));
    val += (d & 1) ? cosf(ang) : sinf(ang);
    g_x[idx] = val;
}

// ---------------- layernorm (tf32-rounded out: feeds GEMMs/QKV) ----------------
__global__ void layernorm_kernel(const float* __restrict__ x, float* __restrict__ out,
                                 const float* __restrict__ g, const float* __restrict__ b){
    __shared__ float sdata[TD];
    int row = blockIdx.x;
    const float* xr = x + (size_t)row*TD;
    float local = 0.f;
    for (int i = threadIdx.x; i < TD; i += 256){ float v = xr[i]; sdata[i] = v; local += v; }
    float mean = blockSum256(local) * (1.0f/TD);
    float lv = 0.f;
    for (int i = threadIdx.x; i < TD; i += 256){ float t = sdata[i]-mean; lv += t*t; }
    float var = blockSum256(lv) * (1.0f/TD);
    float rstd = rsqrtf(var + LN_EPS);
    float* orow = out + (size_t)row*TD;
    for (int i = threadIdx.x; i < TD; i += 256)
        orow[i] = rnd_tf32((sdata[i]-mean)*rstd*g[i] + b[i]);
}

// ---------------- per-head QKV projection ----------------
__global__ void qkv_kernel(const float* __restrict__ Wq, const float* __restrict__ bq,
                           const float* __restrict__ Wk, const float* __restrict__ bk,
                           const float* __restrict__ Wv, const float* __restrict__ bv){
    __shared__ float Hs[64][65];
    __shared__ float Ws[64][64];
    int h = blockIdx.y;
    int m0 = blockIdx.x * 64;
    int tid = threadIdx.x;

    for (int i = tid; i < 64*64; i += 256){
        int r = i >> 6, cc = i & 63;
        int row = m0 + r;
        Hs[r][cc] = (row < M_TOK) ? g_h[(size_t)row*TD + h*64 + cc] : 0.f;
    }
    const float* Wp[3] = {Wq, Wk, Wv};
    const float* bp[3] = {bq, bk, bv};
    float* op[3] = {g_q, g_k, g_v};
    int ty = tid >> 4, tx = tid & 15;

    for (int m = 0; m < 3; m++){
        __syncthreads();
        const float* W = Wp[m] + (size_t)h*64*64;
        for (int i = tid; i < 64*64; i += 256) Ws[i>>6][i&63] = W[i];
        __syncthreads();
        float acc[4][4];
        #pragma unroll
        for (int i=0;i<4;i++)
            #pragma unroll
            for (int j=0;j<4;j++) acc[i][j]=0.f;
        #pragma unroll 8
        for (int kd = 0; kd < 64; kd++){
            float a[4], bb[4];
            #pragma unroll
            for (int i=0;i<4;i++) a[i] = Hs[ty*4+i][kd];
            #pragma unroll
            for (int j=0;j<4;j++) bb[j] = Ws[kd][tx*4+j];
            #pragma unroll
            for (int i=0;i<4;i++)
                #pragma unroll
                for (int j=0;j<4;j++) acc[i][j] = fmaf(a[i], bb[j], acc[i][j]);
        }
        #pragma unroll
        for (int i=0;i<4;i++){
            int row = m0 + ty*4 + i;
            if (row >= M_TOK) continue;
            #pragma unroll
            for (int j=0;j<4;j++){
                int e = tx*4 + j;
                op[m][(size_t)row*TD + h*64 + e] = acc[i][j] + bp[m][h*64 + e];
            }
        }
    }
}

// ---------------- fused attention (per (b,h)), residual add into x ----------------
__global__ void attn_kernel(){
    extern __shared__ float sm[];
    float* Kt = sm;                 // [64][200]
    float* Vs = Kt + 64*200;        // [197][64]
    float* q8 = Vs + TT*64;         // [8][64]
    float* p8 = q8 + 8*64;          // [8][224]

    int h = blockIdx.x, b = blockIdx.y;
    int tid = threadIdx.x;
    size_t base = ((size_t)b*TT)*TD + h*64;

    for (int i = tid; i < TT*64; i += 256){
        int k = i >> 6, d = i & 63;
        float kv = g_k[base + (size_t)k*TD + d];
        Kt[d*200 + k] = kv;
        Vs[i] = g_v[base + (size_t)k*TD + d];
    }
    __syncthreads();

    int w = tid >> 5, lane = tid & 31;
    float* qr = q8 + w*64;
    float* pr = p8 + w*224;

    for (int s = w; s < TT; s += 8){
        qr[lane]      = g_q[base + (size_t)s*TD + lane];
        qr[lane + 32] = g_q[base + (size_t)s*TD + lane + 32];
        __syncwarp();
        float lmax = -1e30f;
        for (int k = lane; k < TT; k += 32){
            float dot = 0.f;
            #pragma unroll
            for (int d = 0; d < 64; d++) dot = fmaf(qr[d], Kt[d*200 + k], dot);
            dot *= ATT_SCALE;
            pr[k] = dot;
            lmax = fmaxf(lmax, dot);
        }
        lmax = warpMax(lmax);
        float lsum = 0.f;
        for (int k = lane; k < TT; k += 32){
            float e = expf(pr[k] - lmax);
            pr[k] = e;
            lsum += e;
        }
        lsum = warpSum(lsum);
        float inv = 1.0f / lsum;
        __syncwarp();
        float acc0 = 0.f, acc1 = 0.f;
        for (int k = 0; k < TT; k++){
            float p = pr[k];
            acc0 = fmaf(p, Vs[k*64 + lane],      acc0);
            acc1 = fmaf(p, Vs[k*64 + lane + 32], acc1);
        }
        size_t xi = base + (size_t)s*TD;
        g_x[xi + lane]      += acc0 * inv;
        g_x[xi + lane + 32] += acc1 * inv;
        __syncwarp();
    }
}

// ---------------- tf32 tensor-core GEMM with cp.async double buffering ----------------
// Inputs MUST be pre-rounded to tf32 (RNA) by producers; inner loop feeds raw bits.
// C (epi) A[M,K] @ B[K,N] + bias ; epi: 0 store, 1 gelu(+tf32 round), 2 residual +=
// block tile 128x128, k-step 16; 256 threads = 8 warps (4x2), warp tile 32x64
// requires N % 128 == 0, K % 16 == 0
__global__ void __launch_bounds__(256)
tf32gemm_kernel(const float* __restrict__ A, const float* __restrict__ Bm,
                const float* __restrict__ bias, float* __restrict__ C,
                int M, int N, int K, int epi){
    __shared__ float As[2][128][20];   // [buf][m][k]
    __shared__ float Bs[2][16][136];   // [buf][k][n]

    int tid  = threadIdx.x;
    int lane = tid & 31;
    int warp = tid >> 5;
    int warpM = warp >> 1;          // 0..3
    int warpN = warp & 1;           // 0..1
    int row0 = blockIdx.y * 128;
    int col0 = blockIdx.x * 128;

    float cf[2][8][4];
    #pragma unroll
    for (int mi=0;mi<2;mi++)
        #pragma unroll
        for (int ni=0;ni<8;ni++)
            #pragma unroll
            for (int j=0;j<4;j++) cf[mi][ni][j] = 0.f;

    int ar = tid >> 2;              // A row 0..63 (and +64)
    int ac = (tid & 3) * 4;         // A col 0,4,8,12
    int bk = tid >> 5;              // B k 0..7 (and +8)
    int bc = (tid & 31) * 4;        // B col 0..124

    int KT = K >> 4;

    // prologue: load tile 0 into buf 0
    {
        #pragma unroll
        for (int half = 0; half < 2; half++){
            int r = ar + half*64;
            int grow = row0 + r;
            cp_async16(smem_u32(&As[0][r][ac]), &A[(size_t)grow*K + ac],
                       (grow < M) ? 16 : 0);
        }
        #pragma unroll
        for (int half = 0; half < 2; half++){
            int k = bk + half*8;
            cp_async16(smem_u32(&Bs[0][k][bc]), &Bm[(size_t)k*N + col0 + bc], 16);
        }
        cp_commit();
    }

    for (int kt = 0; kt < KT; kt++){
        int buf = kt & 1;
        if (kt + 1 < KT){
            int nb = buf ^ 1;
            int kk = (kt + 1) << 4;
            #pragma unroll
            for (int half = 0; half < 2; half++){
                int r = ar + half*64;
                int grow = row0 + r;
                cp_async16(smem_u32(&As[nb][r][ac]), &A[(size_t)grow*K + kk + ac],
                           (grow < M) ? 16 : 0);
            }
            #pragma unroll
            for (int half = 0; half < 2; half++){
                int k = bk + half*8;
                cp_async16(smem_u32(&Bs[nb][k][bc]), &Bm[(size_t)(kk+k)*N + col0 + bc], 16);
            }
            cp_commit();
            cp_wait<1>();
        } else {
            cp_wait<0>();
        }
        __syncthreads();

        #pragma unroll
        for (int ks = 0; ks < 16; ks += 8){
            unsigned af[2][4], bf[8][2];
            #pragma unroll
            for (int mi = 0; mi < 2; mi++){
                int m = warpM*32 + mi*16 + (lane >> 2);
                int k = ks + (lane & 3);
                af[mi][0] = __float_as_uint(As[buf][m][k]);
                af[mi][1] = __float_as_uint(As[buf][m+8][k]);
                af[mi][2] = __float_as_uint(As[buf][m][k+4]);
                af[mi][3] = __float_as_uint(As[buf][m+8][k+4]);
            }
            #pragma unroll
            for (int ni = 0; ni < 8; ni++){
                int n = warpN*64 + ni*8 + (lane >> 2);
                bf[ni][0] = __float_as_uint(Bs[buf][ks     + (lane & 3)][n]);
                bf[ni][1] = __float_as_uint(Bs[buf][ks + 4 + (lane & 3)][n]);
            }
            #pragma unroll
            for (int mi = 0; mi < 2; mi++)
                #pragma unroll
                for (int ni = 0; ni < 8; ni++){
                    asm volatile(
                        "mma.sync.aligned.m16n8k8.row.col.f32.tf32.tf32.f32 "
                        "{%0,%1,%2,%3}, {%4,%5,%6,%7}, {%8,%9}, {%0,%1,%2,%3};"
                        : "+f"(cf[mi][ni][0]), "+f"(cf[mi][ni][1]),
                          "+f"(cf[mi][ni][2]), "+f"(cf[mi][ni][3])
                        : "r"(af[mi][0]), "r"(af[mi][1]), "r"(af[mi][2]), "r"(af[mi][3]),
                          "r"(bf[ni][0]), "r"(bf[ni][1]));
                }
        }
        __syncthreads();
    }

    // epilogue
    #pragma unroll
    for (int mi = 0; mi < 2; mi++){
        int rbase = row0 + warpM*32 + mi*16 + (lane >> 2);
        #pragma unroll
        for (int ni = 0; ni < 8; ni++){
            int cbase = col0 + warpN*64 + ni*8 + (lane & 3)*2;
            #pragma unroll
            for (int hh = 0; hh < 2; hh++){
                int r = rbase + hh*8;
                if (r >= M) continue;
                #pragma unroll
                for (int jj = 0; jj < 2; jj++){
                    int c = cbase + jj;
                    float v = cf[mi][ni][hh*2+jj] + bias[c];
                    size_t idx = (size_t)r*N + c;
                    if (epi == 1){
                        C[idx] = rnd_tf32(0.5f*v*(1.0f + erff(v*0.70710678118654752f)));
                    } else if (epi == 2){
                        C[idx] += v;
                    } else {
                        C[idx] = v;
                    }
                }
            }
        }
    }
}

// ---------------- classifier head + softmax ----------------
__global__ void classifier_kernel(const float* __restrict__ Wout, const float* __restrict__ bout,
                                  float* __restrict__ out){
    __shared__ float xs[TD];
    __shared__ float lg[OD];
    int b = blockIdx.x;
    int tid = threadIdx.x;
    for (int i = tid; i < TD; i += 256) xs[i] = g_x[((size_t)b*TT)*TD + i];
    __syncthreads();
    for (int n = tid; n < OD; n += 256){
        float s = bout[n];
        for (int d = 0; d < TD; d++) s = fmaf(xs[d], Wout[(size_t)d*OD + n], s);
        lg[n] = s;
    }
    __syncthreads();
    float lm = -1e30f;
    for (int n = tid; n < OD; n += 256) lm = fmaxf(lm, lg[n]);
    lm = blockMax256(lm);
    float ls = 0.f;
    for (int n = tid; n < OD; n += 256){
        float e = expf(lg[n] - lm);
        lg[n] = e;
        ls += e;
    }
    ls = blockSum256(ls);
    float inv = 1.0f / ls;
    for (int n = tid; n < OD; n += 256) out[(size_t)b*OD + n] = lg[n] * inv;
}

// ---------------- host orchestration ----------------
extern "C" void kernel_launch(void* const* d_in, const int* in_sizes, int n_in,
                              void* d_out, int out_size){
    const float* images  = (const float*)d_in[0];
    const float* W_embed = (const float*)d_in[1];
    const float* b_embed = (const float*)d_in[2];
    const float* v_class = (const float*)d_in[3];
    const float* ln1_g   = (const float*)d_in[4];
    const float* ln1_b   = (const float*)d_in[5];
    const float* ln2_g   = (const float*)d_in[6];
    const float* ln2_b   = (const float*)d_in[7];
    const float* Wq      = (const float*)d_in[8];
    const float* bq      = (const float*)d_in[9];
    const float* Wk      = (const float*)d_in[10];
    const float* bk      = (const float*)d_in[11];
    const float* Wv      = (const float*)d_in[12];
    const float* bv      = (const float*)d_in[13];
    const float* Wm1     = (const float*)d_in[14];
    const float* bm1     = (const float*)d_in[15];
    const float* Wm2     = (const float*)d_in[16];
    const float* bm2     = (const float*)d_in[17];
    const float* Wout    = (const float*)d_in[18];
    const float* bout    = (const float*)d_in[19];
    float* out = (float*)d_out;

    float *px, *ph, *pmlp, *ppatch, *pwR;
    cudaGetSymbolAddress((void**)&px, g_x);
    cudaGetSymbolAddress((void**)&ph, g_h);
    cudaGetSymbolAddress((void**)&pmlp, g_mlp);
    cudaGetSymbolAddress((void**)&ppatch, g_patches);
    cudaGetSymbolAddress((void**)&pwR, g_wR);

    const int ATT_SMEM = (64*200 + TT*64 + 8*64 + 8*224) * 4; // 110848 bytes
    cudaFuncSetAttribute(attn_kernel, cudaFuncAttributeMaxDynamicSharedMemorySize, ATT_SMEM);

    // round weights to tf32 once per launch (keeps [K][N] orientation)
    roundcopy_kernel<<<2048, 256>>>(W_embed, pwR + WR_EMBED_OFF, (size_t)TD*TD);
    roundcopy_kernel<<<16384, 256>>>(Wm1, pwR + WR_M1_OFF, (size_t)NB*TD*MD);
    roundcopy_kernel<<<16384, 256>>>(Wm2, pwR + WR_M2_OFF, (size_t)NB*MD*TD);

    // patchify + embed
    patchify_kernel<<<(M_PATCH*TD + 255)/256, 256>>>(images);
    {
        dim3 g(TD/128, (M_PATCH + 127)/128);
        tf32gemm_kernel<<<g, 256>>>(ppatch, pwR + WR_EMBED_OFF, b_embed, pmlp,
                                    M_PATCH, TD, TD, 0);
    }
    assemble_kernel<<<(M_TOK*TD + 255)/256, 256>>>(v_class, pmlp);

    for (int l = 0; l < NB; l++){
        layernorm_kernel<<<M_TOK, 256>>>(px, ph, ln1_g + l*TD, ln1_b + l*TD);
        {
            dim3 g((M_TOK + 63)/64, NH);
            qkv_kernel<<<g, 256>>>(Wq + (size_t)l*NH*64*64, bq + (size_t)l*NH*64,
                                   Wk + (size_t)l*NH*64*64, bk + (size_t)l*NH*64,
                                   Wv + (size_t)l*NH*64*64, bv + (size_t)l*NH*64);
        }
        attn_kernel<<<dim3(NH, BSZ), 256, ATT_SMEM>>>();
        layernorm_kernel<<<M_TOK, 256>>>(px, ph, ln2_g + l*TD, ln2_b + l*TD);
        {
            dim3 g(MD/128, (M_TOK + 127)/128);
            tf32gemm_kernel<<<g, 256>>>(ph, pwR + WR_M1_OFF + (size_t)l*TD*MD,
                                        bm1 + (size_t)l*MD, pmlp,
                                        M_TOK, MD, TD, 1);
        }
        {
            dim3 g(TD/128, (M_TOK + 127)/128);
            tf32gemm_kernel<<<g, 256>>>(pmlp, pwR + WR_M2_OFF + (size_t)l*MD*TD,
                                        bm2 + (size_t)l*TD, px,
                                        M_TOK, TD, MD, 2);
        }
    }

    classifier_kernel<<<BSZ, 256>>>(Wout, bout, out);
}